// round 4
// baseline (speedup 1.0000x reference)
#include <cuda_runtime.h>
#include <cuda_bf16.h>

#define BB 1024
#define TT 256
#define VV 256
#define HH 32

// hs scratch, DUPLICATED layout: g_hs[row][2k] = g_hs[row][2k+1] = h[row][k]
// (row = t*B + b). 67 MB. Written as (h,h) pairs by kernel A so kernel B can
// feed fma.rn.f32x2 without splat MOVs.
__device__ float g_hs[TT * BB * 2 * HH];

__device__ __forceinline__ float htanh(float x) {
    float y;
    asm("tanh.approx.f32 %0, %1;" : "=f"(y) : "f"(x));
    return y;
}

// ---------------------------------------------------------------------------
// Kernel A: embedding gather + recurrence. One warp per batch element,
// h[j] in lane j; h broadcast via double-buffered SMEM vector.
// 8 FFMA chains (depth 4) + tree reduce. Writes dup pairs (STG.64).
// ---------------------------------------------------------------------------
__global__ void __launch_bounds__(256)
rnn_recurrence(const int* __restrict__ X, const float* __restrict__ Wxh,
               const float* __restrict__ Whh, const float* __restrict__ bh)
{
    __shared__ float sWxh[VV * HH];       // 32 KB
    __shared__ int   sX[8][TT];           // 8 KB
    __shared__ float sH[2][8][HH];        // 2 KB double-buffered h vectors

    const int tid  = threadIdx.x;
    const int lane = tid & 31;
    const int warp = tid >> 5;
    const int b    = blockIdx.x * 8 + warp;

    {
        const float4* s = (const float4*)Wxh;
        float4*       d = (float4*)sWxh;
        #pragma unroll
        for (int i = tid; i < (VV * HH) / 4; i += 256) d[i] = s[i];
    }
    {
        const int4* s = (const int4*)(X + (long)blockIdx.x * 8 * TT);
        int4*       d = (int4*)&sX[0][0];
        #pragma unroll
        for (int i = tid; i < (8 * TT) / 4; i += 256) d[i] = s[i];
    }

    float w[HH];
    #pragma unroll
    for (int i = 0; i < HH; i++) w[i] = Whh[i * HH + lane];
    const float bhv = bh[lane];

    sH[0][warp][lane] = 0.f;
    __syncthreads();

    float2* outp = (float2*)(g_hs + (long)b * (2 * HH)) + lane;

    int   tok = sX[warp][0];
    float xe  = sWxh[tok * HH + lane];

    #pragma unroll 2
    for (int t = 0; t < TT; t++) {
        const int tokn = sX[warp][(t + 1) & (TT - 1)];

        const float4* hr = (const float4*)&sH[t & 1][warp][0];
        float4 hv[8];
        #pragma unroll
        for (int k = 0; k < 8; k++) hv[k] = hr[k];

        // 8 independent FFMA chains of depth 4
        float a[8];
        #pragma unroll
        for (int k = 0; k < 8; k++) a[k] = 0.f;
        #pragma unroll
        for (int k = 0; k < 8; k += 2) {
            a[k+0] = fmaf(hv[k+0].x, w[4*k + 0], a[k+0]);
            a[k+1] = fmaf(hv[k+0].y, w[4*k + 1], a[k+1]);
            a[k+0] = fmaf(hv[k+0].z, w[4*k + 2], a[k+0]);
            a[k+1] = fmaf(hv[k+0].w, w[4*k + 3], a[k+1]);
            a[k+0] = fmaf(hv[k+1].x, w[4*k + 4], a[k+0]);
            a[k+1] = fmaf(hv[k+1].y, w[4*k + 5], a[k+1]);
            a[k+0] = fmaf(hv[k+1].z, w[4*k + 6], a[k+0]);
            a[k+1] = fmaf(hv[k+1].w, w[4*k + 7], a[k+1]);
        }
        float s = (xe + bhv)
                + (((a[0] + a[1]) + (a[2] + a[3]))
                +  ((a[4] + a[5]) + (a[6] + a[7])));

        xe = sWxh[tokn * HH + lane];

        const float h = htanh(s);
        sH[(t + 1) & 1][warp][lane] = h;
        outp[(long)t * (BB * HH)] = make_float2(h, h);  // dup pair, coalesced
        __syncwarp();
    }
}

// ---------------------------------------------------------------------------
// packed f32x2 helpers
// ---------------------------------------------------------------------------
__device__ __forceinline__ unsigned long long pair_of(float x, float y) {
    unsigned long long r;
    asm("mov.b64 %0, {%1, %2};" : "=l"(r) : "f"(x), "f"(y));
    return r;
}
__device__ __forceinline__ unsigned long long fma2(unsigned long long a,
                                                   unsigned long long b,
                                                   unsigned long long c) {
    unsigned long long d;
    asm("fma.rn.f32x2 %0, %1, %2, %3;" : "=l"(d) : "l"(a), "l"(b), "l"(c));
    return d;
}
__device__ __forceinline__ float2 unpack2(unsigned long long u) {
    float2 f;
    asm("mov.b64 {%0, %1}, %2;" : "=f"(f.x), "=f"(f.y) : "l"(u));
    return f;
}

// ---------------------------------------------------------------------------
// Kernel B: logits[b][t][v] = sum_h hs[t][b][h] * Whq[h][v] + bq[v]
// 256 thr / 8 warps; each warp: 8 rows x FULL V=256 (lane owns v in
// [8L, 8L+8), i.e. 4 fma2 pairs). Block = 64 rows.
// Per k2 (2 k-steps): 4 W-LDS.128 + 8 dup-h LDS.128 (broadcast) + 64 fma2.
// No shuffles, no splats. Bias folded into acc init.
// ---------------------------------------------------------------------------
__global__ void __launch_bounds__(256, 2)
rnn_logits(const float* __restrict__ Whq, const float* __restrict__ bq,
           float* __restrict__ out)
{
    __shared__ float sW[HH * VV];          // 32 KB, [h][v]
    __shared__ float sHs[64 * 2 * HH];     // 16 KB, 64 dup rows

    const int tid  = threadIdx.x;
    const int lane = tid & 31;
    const int warp = tid >> 5;

    {
        const float4* s = (const float4*)Whq;
        float4*       d = (float4*)sW;
        #pragma unroll
        for (int i = tid; i < (HH * VV) / 4; i += 256) d[i] = s[i];
    }
    {
        const float4* s = (const float4*)(g_hs + (long)blockIdx.x * 64 * (2 * HH));
        float4*       d = (float4*)sHs;
        #pragma unroll
        for (int i = tid; i < (64 * 2 * HH) / 4; i += 256) d[i] = s[i];
    }

    // bias for lane's v in [8L, 8L+8): 2 LDG.128 -> 4 pairs
    const float4 bqa = ((const float4*)bq)[2 * lane + 0];
    const float4 bqb = ((const float4*)bq)[2 * lane + 1];

    __syncthreads();

    const float4* sW4 = (const float4*)sW;                       // 64 f4 per k-row
    const float4* sH4 = (const float4*)(sHs + warp * 8 * (2 * HH)); // 16 f4 per row

    unsigned long long acc[8][4];
    #pragma unroll
    for (int r = 0; r < 8; r++) {
        acc[r][0] = pair_of(bqa.x, bqa.y);
        acc[r][1] = pair_of(bqa.z, bqa.w);
        acc[r][2] = pair_of(bqb.x, bqb.y);
        acc[r][3] = pair_of(bqb.z, bqb.w);
    }

    #pragma unroll
    for (int k2 = 0; k2 < HH / 2; k2++) {
        // W rows for k = 2*k2 and 2*k2+1, lane's 8 v
        const float4 wA0 = sW4[(2 * k2 + 0) * 64 + 2 * lane + 0];
        const float4 wA1 = sW4[(2 * k2 + 0) * 64 + 2 * lane + 1];
        const float4 wB0 = sW4[(2 * k2 + 1) * 64 + 2 * lane + 0];
        const float4 wB1 = sW4[(2 * k2 + 1) * 64 + 2 * lane + 1];
        const unsigned long long wa0 = pair_of(wA0.x, wA0.y);
        const unsigned long long wa1 = pair_of(wA0.z, wA0.w);
        const unsigned long long wa2 = pair_of(wA1.x, wA1.y);
        const unsigned long long wa3 = pair_of(wA1.z, wA1.w);
        const unsigned long long wb0 = pair_of(wB0.x, wB0.y);
        const unsigned long long wb1 = pair_of(wB0.z, wB0.w);
        const unsigned long long wb2 = pair_of(wB1.x, wB1.y);
        const unsigned long long wb3 = pair_of(wB1.z, wB1.w);

        #pragma unroll
        for (int r = 0; r < 8; r++) {
            // dup layout: float4 k2 of row r = (hA, hA, hB, hB)
            const float4 hp = sH4[r * 16 + k2];      // broadcast LDS.128
            const unsigned long long ha = pair_of(hp.x, hp.y);
            const unsigned long long hb = pair_of(hp.z, hp.w);
            acc[r][0] = fma2(ha, wa0, acc[r][0]);
            acc[r][1] = fma2(ha, wa1, acc[r][1]);
            acc[r][2] = fma2(ha, wa2, acc[r][2]);
            acc[r][3] = fma2(ha, wa3, acc[r][3]);
            acc[r][0] = fma2(hb, wb0, acc[r][0]);
            acc[r][1] = fma2(hb, wb1, acc[r][1]);
            acc[r][2] = fma2(hb, wb2, acc[r][2]);
            acc[r][3] = fma2(hb, wb3, acc[r][3]);
        }
    }

    // epilogue: lane writes v = 8L..8L+7 as 2x STG.128 per row
    #pragma unroll
    for (int r = 0; r < 8; r++) {
        const long row = (long)blockIdx.x * 64 + warp * 8 + r;  // row = t*B + b
        const int  t   = (int)(row >> 10);                       // B = 1024
        const int  b   = (int)(row & 1023);
        float4* o = (float4*)(out + (((long)b * TT + t) * VV) + 8 * lane);
        const float2 f0 = unpack2(acc[r][0]);
        const float2 f1 = unpack2(acc[r][1]);
        const float2 f2 = unpack2(acc[r][2]);
        const float2 f3 = unpack2(acc[r][3]);
        o[0] = make_float4(f0.x, f0.y, f1.x, f1.y);
        o[1] = make_float4(f2.x, f2.y, f3.x, f3.y);
    }
}

// ---------------------------------------------------------------------------
// kernel_launch
// inputs: 0:X int32[B,T]  1:W_xh f32[V,H]  2:W_hh f32[H,H]  3:b_h f32[H]
//         4:W_hq f32[H,V] 5:b_q f32[V]     out: f32[B,T,V]
// ---------------------------------------------------------------------------
extern "C" void kernel_launch(void* const* d_in, const int* in_sizes, int n_in,
                              void* d_out, int out_size)
{
    const int*   X   = (const int*)d_in[0];
    const float* Wxh = (const float*)d_in[1];
    const float* Whh = (const float*)d_in[2];
    const float* bh  = (const float*)d_in[3];
    const float* Whq = (const float*)d_in[4];
    const float* bq  = (const float*)d_in[5];
    float*       out = (float*)d_out;

    rnn_recurrence<<<BB / 8, 256>>>(X, Wxh, Whh, bh);
    rnn_logits<<<(TT * BB) / 64, 256>>>(Whq, bq, out);
}

// round 5
// speedup vs baseline: 1.0046x; 1.0046x over previous
#include <cuda_runtime.h>
#include <cuda_bf16.h>

#define BB 1024
#define TT 256
#define VV 256
#define HH 32

// hs scratch, DUPLICATED layout: g_hs[row][2k] = g_hs[row][2k+1] = h[row][k]
// (row = t*B + b). Written as (h,h) pairs so kernel B feeds fma.rn.f32x2
// without splat MOVs.
__device__ float g_hs[TT * BB * 2 * HH];

__device__ __forceinline__ float htanh(float x) {
    float y;
    asm("tanh.approx.f32 %0, %1;" : "=f"(y) : "f"(x));
    return y;
}

// ---------------------------------------------------------------------------
// Kernel A: embedding gather + recurrence (round-4 version, ~30us).
// ---------------------------------------------------------------------------
__global__ void __launch_bounds__(256)
rnn_recurrence(const int* __restrict__ X, const float* __restrict__ Wxh,
               const float* __restrict__ Whh, const float* __restrict__ bh)
{
    __shared__ float sWxh[VV * HH];       // 32 KB
    __shared__ int   sX[8][TT];           // 8 KB
    __shared__ float sH[2][8][HH];        // 2 KB double-buffered h vectors

    const int tid  = threadIdx.x;
    const int lane = tid & 31;
    const int warp = tid >> 5;
    const int b    = blockIdx.x * 8 + warp;

    {
        const float4* s = (const float4*)Wxh;
        float4*       d = (float4*)sWxh;
        #pragma unroll
        for (int i = tid; i < (VV * HH) / 4; i += 256) d[i] = s[i];
    }
    {
        const int4* s = (const int4*)(X + (long)blockIdx.x * 8 * TT);
        int4*       d = (int4*)&sX[0][0];
        #pragma unroll
        for (int i = tid; i < (8 * TT) / 4; i += 256) d[i] = s[i];
    }

    float w[HH];
    #pragma unroll
    for (int i = 0; i < HH; i++) w[i] = Whh[i * HH + lane];
    const float bhv = bh[lane];

    sH[0][warp][lane] = 0.f;
    __syncthreads();

    float2* outp = (float2*)(g_hs + (long)b * (2 * HH)) + lane;

    int   tok = sX[warp][0];
    float xe  = sWxh[tok * HH + lane];

    #pragma unroll 2
    for (int t = 0; t < TT; t++) {
        const int tokn = sX[warp][(t + 1) & (TT - 1)];

        const float4* hr = (const float4*)&sH[t & 1][warp][0];
        float4 hv[8];
        #pragma unroll
        for (int k = 0; k < 8; k++) hv[k] = hr[k];

        float a[8];
        #pragma unroll
        for (int k = 0; k < 8; k++) a[k] = 0.f;
        #pragma unroll
        for (int k = 0; k < 8; k += 2) {
            a[k+0] = fmaf(hv[k+0].x, w[4*k + 0], a[k+0]);
            a[k+1] = fmaf(hv[k+0].y, w[4*k + 1], a[k+1]);
            a[k+0] = fmaf(hv[k+0].z, w[4*k + 2], a[k+0]);
            a[k+1] = fmaf(hv[k+0].w, w[4*k + 3], a[k+1]);
            a[k+0] = fmaf(hv[k+1].x, w[4*k + 4], a[k+0]);
            a[k+1] = fmaf(hv[k+1].y, w[4*k + 5], a[k+1]);
            a[k+0] = fmaf(hv[k+1].z, w[4*k + 6], a[k+0]);
            a[k+1] = fmaf(hv[k+1].w, w[4*k + 7], a[k+1]);
        }
        float s = (xe + bhv)
                + (((a[0] + a[1]) + (a[2] + a[3]))
                +  ((a[4] + a[5]) + (a[6] + a[7])));

        xe = sWxh[tokn * HH + lane];

        const float h = htanh(s);
        sH[(t + 1) & 1][warp][lane] = h;
        outp[(long)t * (BB * HH)] = make_float2(h, h);
        __syncwarp();
    }
}

// ---------------------------------------------------------------------------
// packed f32x2 helpers
// ---------------------------------------------------------------------------
__device__ __forceinline__ unsigned long long pair_of(float x, float y) {
    unsigned long long r;
    asm("mov.b64 %0, {%1, %2};" : "=l"(r) : "f"(x), "f"(y));
    return r;
}
__device__ __forceinline__ unsigned long long fma2(unsigned long long a,
                                                   unsigned long long b,
                                                   unsigned long long c) {
    unsigned long long d;
    asm("fma.rn.f32x2 %0, %1, %2, %3;" : "=l"(d) : "l"(a), "l"(b), "l"(c));
    return d;
}
__device__ __forceinline__ float2 unpack2(unsigned long long u) {
    float2 f;
    asm("mov.b64 {%0, %1}, %2;" : "=f"(f.x), "=f"(f.y) : "l"(u));
    return f;
}

// ---------------------------------------------------------------------------
// Kernel B: logits[b][t][v] = sum_h hs[t][b][h] * Whq[h][v] + bq[v]
// 256 thr / 8 warps; warp = 8 rows x full V=256.
// Lane L owns v in [4L, 4L+4) and [128+4L, 128+4L+4):
//   W per k = 2 coalesced LDS.128 at byte 16L (conflict-free, 4 wf each)
//   h per k2 per row = 1 broadcast LDS.128 of dup pairs (1 wf)
// Per k2: 24 smem wavefronts vs 32 SM-cycles of fma2 -> fma-bound.
// ---------------------------------------------------------------------------
__global__ void __launch_bounds__(256, 2)
rnn_logits(const float* __restrict__ Whq, const float* __restrict__ bq,
           float* __restrict__ out)
{
    __shared__ float sW[HH * VV];          // 32 KB, [h][v]
    __shared__ float sHs[64 * 2 * HH];     // 16 KB, 64 dup rows

    const int tid  = threadIdx.x;
    const int lane = tid & 31;
    const int warp = tid >> 5;

    {
        const float4* s = (const float4*)Whq;
        float4*       d = (float4*)sW;
        #pragma unroll
        for (int i = tid; i < (HH * VV) / 4; i += 256) d[i] = s[i];
    }
    {
        const float4* s = (const float4*)(g_hs + (long)blockIdx.x * 64 * (2 * HH));
        float4*       d = (float4*)sHs;
        #pragma unroll
        for (int i = tid; i < (64 * 2 * HH) / 4; i += 256) d[i] = s[i];
    }

    // bias: lane's v = [4L,4L+4) and [128+4L,128+4L+4)
    const float4 bqa = ((const float4*)bq)[lane];
    const float4 bqb = ((const float4*)bq)[32 + lane];

    __syncthreads();

    const float4* sW4 = (const float4*)sW;                          // 64 f4/k-row
    const float4* sH4 = (const float4*)(sHs + warp * 8 * (2 * HH)); // 16 f4/row

    unsigned long long acc[8][4];
    #pragma unroll
    for (int r = 0; r < 8; r++) {
        acc[r][0] = pair_of(bqa.x, bqa.y);
        acc[r][1] = pair_of(bqa.z, bqa.w);
        acc[r][2] = pair_of(bqb.x, bqb.y);
        acc[r][3] = pair_of(bqb.z, bqb.w);
    }

    #pragma unroll
    for (int k2 = 0; k2 < HH / 2; k2++) {
        // W rows k = 2*k2, 2*k2+1 — coalesced: lane L reads float4 at index L
        const float4 wA0 = sW4[(2 * k2 + 0) * 64 + lane];        // v 4L..4L+3
        const float4 wA1 = sW4[(2 * k2 + 0) * 64 + 32 + lane];   // v 128+4L..
        const float4 wB0 = sW4[(2 * k2 + 1) * 64 + lane];
        const float4 wB1 = sW4[(2 * k2 + 1) * 64 + 32 + lane];
        const unsigned long long wa0 = pair_of(wA0.x, wA0.y);
        const unsigned long long wa1 = pair_of(wA0.z, wA0.w);
        const unsigned long long wa2 = pair_of(wA1.x, wA1.y);
        const unsigned long long wa3 = pair_of(wA1.z, wA1.w);
        const unsigned long long wb0 = pair_of(wB0.x, wB0.y);
        const unsigned long long wb1 = pair_of(wB0.z, wB0.w);
        const unsigned long long wb2 = pair_of(wB1.x, wB1.y);
        const unsigned long long wb3 = pair_of(wB1.z, wB1.w);

        #pragma unroll
        for (int r = 0; r < 8; r++) {
            // dup layout: float4 #k2 of row r = (hA, hA, hB, hB)
            const float4 hp = sH4[r * 16 + k2];     // broadcast, 1 wf
            const unsigned long long ha = pair_of(hp.x, hp.y);
            const unsigned long long hb = pair_of(hp.z, hp.w);
            acc[r][0] = fma2(ha, wa0, acc[r][0]);
            acc[r][1] = fma2(ha, wa1, acc[r][1]);
            acc[r][2] = fma2(ha, wa2, acc[r][2]);
            acc[r][3] = fma2(ha, wa3, acc[r][3]);
            acc[r][0] = fma2(hb, wb0, acc[r][0]);
            acc[r][1] = fma2(hb, wb1, acc[r][1]);
            acc[r][2] = fma2(hb, wb2, acc[r][2]);
            acc[r][3] = fma2(hb, wb3, acc[r][3]);
        }
    }

    // epilogue: 2 STG.128 per row (v segs [4L,4L+4) and [128+4L, ...))
    #pragma unroll
    for (int r = 0; r < 8; r++) {
        const long row = (long)blockIdx.x * 64 + warp * 8 + r;  // row = t*B + b
        const int  t   = (int)(row >> 10);                       // B = 1024
        const int  b   = (int)(row & 1023);
        float* obase = out + (((long)b * TT + t) * VV);
        const float2 f0 = unpack2(acc[r][0]);
        const float2 f1 = unpack2(acc[r][1]);
        const float2 f2 = unpack2(acc[r][2]);
        const float2 f3 = unpack2(acc[r][3]);
        ((float4*)(obase))[lane]      = make_float4(f0.x, f0.y, f1.x, f1.y);
        ((float4*)(obase))[32 + lane] = make_float4(f2.x, f2.y, f3.x, f3.y);
    }
}

// ---------------------------------------------------------------------------
// kernel_launch
// inputs: 0:X int32[B,T]  1:W_xh f32[V,H]  2:W_hh f32[H,H]  3:b_h f32[H]
//         4:W_hq f32[H,V] 5:b_q f32[V]     out: f32[B,T,V]
// ---------------------------------------------------------------------------
extern "C" void kernel_launch(void* const* d_in, const int* in_sizes, int n_in,
                              void* d_out, int out_size)
{
    const int*   X   = (const int*)d_in[0];
    const float* Wxh = (const float*)d_in[1];
    const float* Whh = (const float*)d_in[2];
    const float* bh  = (const float*)d_in[3];
    const float* Whq = (const float*)d_in[4];
    const float* bq  = (const float*)d_in[5];
    float*       out = (float*)d_out;

    rnn_recurrence<<<BB / 8, 256>>>(X, Wxh, Whh, bh);
    rnn_logits<<<(TT * BB) / 64, 256>>>(Whq, bq, out);
}

// round 6
// speedup vs baseline: 1.0957x; 1.0906x over previous
#include <cuda_runtime.h>
#include <cuda_bf16.h>

#define BB 1024
#define TT 256
#define VV 256
#define HH 32

// hs scratch, DUPLICATED layout: g_hs[row][2k] = g_hs[row][2k+1] = h[row][k]
// (row = t*B + b). Written as (h,h) pairs so kernel B feeds fma.rn.f32x2
// without splat MOVs.
__device__ float g_hs[TT * BB * 2 * HH];

__device__ __forceinline__ float htanh(float x) {
    float y;
    asm("tanh.approx.f32 %0, %1;" : "=f"(y) : "f"(x));
    return y;
}

// ---------------------------------------------------------------------------
// Kernel A: embedding gather + recurrence (unchanged, ~31us).
// ---------------------------------------------------------------------------
__global__ void __launch_bounds__(256)
rnn_recurrence(const int* __restrict__ X, const float* __restrict__ Wxh,
               const float* __restrict__ Whh, const float* __restrict__ bh)
{
    __shared__ float sWxh[VV * HH];       // 32 KB
    __shared__ int   sX[8][TT];           // 8 KB
    __shared__ float sH[2][8][HH];        // 2 KB double-buffered h vectors

    const int tid  = threadIdx.x;
    const int lane = tid & 31;
    const int warp = tid >> 5;
    const int b    = blockIdx.x * 8 + warp;

    {
        const float4* s = (const float4*)Wxh;
        float4*       d = (float4*)sWxh;
        #pragma unroll
        for (int i = tid; i < (VV * HH) / 4; i += 256) d[i] = s[i];
    }
    {
        const int4* s = (const int4*)(X + (long)blockIdx.x * 8 * TT);
        int4*       d = (int4*)&sX[0][0];
        #pragma unroll
        for (int i = tid; i < (8 * TT) / 4; i += 256) d[i] = s[i];
    }

    float w[HH];
    #pragma unroll
    for (int i = 0; i < HH; i++) w[i] = Whh[i * HH + lane];
    const float bhv = bh[lane];

    sH[0][warp][lane] = 0.f;
    __syncthreads();

    float2* outp = (float2*)(g_hs + (long)b * (2 * HH)) + lane;

    int   tok = sX[warp][0];
    float xe  = sWxh[tok * HH + lane];

    #pragma unroll 2
    for (int t = 0; t < TT; t++) {
        const int tokn = sX[warp][(t + 1) & (TT - 1)];

        const float4* hr = (const float4*)&sH[t & 1][warp][0];
        float4 hv[8];
        #pragma unroll
        for (int k = 0; k < 8; k++) hv[k] = hr[k];

        float a[8];
        #pragma unroll
        for (int k = 0; k < 8; k++) a[k] = 0.f;
        #pragma unroll
        for (int k = 0; k < 8; k += 2) {
            a[k+0] = fmaf(hv[k+0].x, w[4*k + 0], a[k+0]);
            a[k+1] = fmaf(hv[k+0].y, w[4*k + 1], a[k+1]);
            a[k+0] = fmaf(hv[k+0].z, w[4*k + 2], a[k+0]);
            a[k+1] = fmaf(hv[k+0].w, w[4*k + 3], a[k+1]);
            a[k+0] = fmaf(hv[k+1].x, w[4*k + 4], a[k+0]);
            a[k+1] = fmaf(hv[k+1].y, w[4*k + 5], a[k+1]);
            a[k+0] = fmaf(hv[k+1].z, w[4*k + 6], a[k+0]);
            a[k+1] = fmaf(hv[k+1].w, w[4*k + 7], a[k+1]);
        }
        float s = (xe + bhv)
                + (((a[0] + a[1]) + (a[2] + a[3]))
                +  ((a[4] + a[5]) + (a[6] + a[7])));

        xe = sWxh[tokn * HH + lane];

        const float h = htanh(s);
        sH[(t + 1) & 1][warp][lane] = h;
        outp[(long)t * (BB * HH)] = make_float2(h, h);
        __syncwarp();
    }
}

// ---------------------------------------------------------------------------
// packed f32x2 helpers
// ---------------------------------------------------------------------------
__device__ __forceinline__ unsigned long long pair_of(float x, float y) {
    unsigned long long r;
    asm("mov.b64 %0, {%1, %2};" : "=l"(r) : "f"(x), "f"(y));
    return r;
}
__device__ __forceinline__ unsigned long long fma2(unsigned long long a,
                                                   unsigned long long b,
                                                   unsigned long long c) {
    unsigned long long d;
    asm("fma.rn.f32x2 %0, %1, %2, %3;" : "=l"(d) : "l"(a), "l"(b), "l"(c));
    return d;
}
__device__ __forceinline__ float2 unpack2(unsigned long long u) {
    float2 f;
    asm("mov.b64 {%0, %1}, %2;" : "=f"(f.x), "=f"(f.y) : "l"(u));
    return f;
}

// cp.async 16B
__device__ __forceinline__ void cp16(unsigned smem_addr, const void* gptr) {
    asm volatile("cp.async.ca.shared.global [%0], [%1], 16;"
                 :: "r"(smem_addr), "l"(gptr));
}

// ---------------------------------------------------------------------------
// Kernel B: logits[b][t][v] = sum_h hs[t][b][h] * Whq[h][v] + bq[v]
// Persistent-ish: 1024 blocks x 4 chunks of 64 rows. W_hq staged to SMEM once
// per block; hs chunks double-buffered via cp.async (prefetch chunk c+1 while
// computing chunk c). Inner loop = round-5 conflict-free layout:
// warp = 8 rows x full V; lane owns v in [4L,4L+4) u [128+4L,128+4L+4).
// ---------------------------------------------------------------------------
#define CHUNKS 4
#define CROWS  64

__global__ void __launch_bounds__(256, 2)
rnn_logits(const float* __restrict__ Whq, const float* __restrict__ bq,
           float* __restrict__ out)
{
    __shared__ float sW[HH * VV];                 // 32 KB, [h][v]
    __shared__ float sHs[2][CROWS * 2 * HH];      // 2 x 16 KB dup-h chunks

    const int tid  = threadIdx.x;
    const int lane = tid & 31;
    const int warp = tid >> 5;

    // stage W once per block
    {
        const float4* s = (const float4*)Whq;
        float4*       d = (float4*)sW;
        #pragma unroll
        for (int i = tid; i < (HH * VV) / 4; i += 256) d[i] = s[i];
    }

    // bias: lane's v = [4L,4L+4) and [128+4L,128+4L+4)
    const float4 bqa = ((const float4*)bq)[lane];
    const float4 bqb = ((const float4*)bq)[32 + lane];

    const float* gbase = g_hs + (long)blockIdx.x * CHUNKS * CROWS * (2 * HH);

    // prefetch chunk 0 into buffer 0 (16 KB = 1024 x 16B; 4 per thread)
    {
        unsigned sdst = (unsigned)__cvta_generic_to_shared(&sHs[0][0]);
        #pragma unroll
        for (int i = 0; i < 4; i++) {
            const int j = tid + i * 256;
            cp16(sdst + j * 16, (const char*)gbase + (long)j * 16);
        }
        asm volatile("cp.async.commit_group;");
    }

    const float4* sW4 = (const float4*)sW;   // 64 f4 per k-row

    for (int c = 0; c < CHUNKS; c++) {
        // prefetch chunk c+1 into alternate buffer
        if (c + 1 < CHUNKS) {
            unsigned sdst = (unsigned)__cvta_generic_to_shared(&sHs[(c + 1) & 1][0]);
            const char* gsrc = (const char*)(gbase + (long)(c + 1) * CROWS * (2 * HH));
            #pragma unroll
            for (int i = 0; i < 4; i++) {
                const int j = tid + i * 256;
                cp16(sdst + j * 16, gsrc + (long)j * 16);
            }
            asm volatile("cp.async.commit_group;");
            asm volatile("cp.async.wait_group 1;");
        } else {
            asm volatile("cp.async.wait_group 0;");
        }
        __syncthreads();   // chunk c visible to all; prior reads of buf (c+1)&1 done

        const float4* sH4 = (const float4*)(&sHs[c & 1][0] + warp * 8 * (2 * HH));

        unsigned long long acc[8][4];
        #pragma unroll
        for (int r = 0; r < 8; r++) {
            acc[r][0] = pair_of(bqa.x, bqa.y);
            acc[r][1] = pair_of(bqa.z, bqa.w);
            acc[r][2] = pair_of(bqb.x, bqb.y);
            acc[r][3] = pair_of(bqb.z, bqb.w);
        }

        #pragma unroll
        for (int k2 = 0; k2 < HH / 2; k2++) {
            const float4 wA0 = sW4[(2 * k2 + 0) * 64 + lane];
            const float4 wA1 = sW4[(2 * k2 + 0) * 64 + 32 + lane];
            const float4 wB0 = sW4[(2 * k2 + 1) * 64 + lane];
            const float4 wB1 = sW4[(2 * k2 + 1) * 64 + 32 + lane];
            const unsigned long long wa0 = pair_of(wA0.x, wA0.y);
            const unsigned long long wa1 = pair_of(wA0.z, wA0.w);
            const unsigned long long wa2 = pair_of(wA1.x, wA1.y);
            const unsigned long long wa3 = pair_of(wA1.z, wA1.w);
            const unsigned long long wb0 = pair_of(wB0.x, wB0.y);
            const unsigned long long wb1 = pair_of(wB0.z, wB0.w);
            const unsigned long long wb2 = pair_of(wB1.x, wB1.y);
            const unsigned long long wb3 = pair_of(wB1.z, wB1.w);

            #pragma unroll
            for (int r = 0; r < 8; r++) {
                // dup layout: float4 #k2 of row r = (hA, hA, hB, hB)
                const float4 hp = sH4[r * 16 + k2];     // broadcast, 1 wf
                const unsigned long long ha = pair_of(hp.x, hp.y);
                const unsigned long long hb = pair_of(hp.z, hp.w);
                acc[r][0] = fma2(ha, wa0, acc[r][0]);
                acc[r][1] = fma2(ha, wa1, acc[r][1]);
                acc[r][2] = fma2(ha, wa2, acc[r][2]);
                acc[r][3] = fma2(ha, wa3, acc[r][3]);
                acc[r][0] = fma2(hb, wb0, acc[r][0]);
                acc[r][1] = fma2(hb, wb1, acc[r][1]);
                acc[r][2] = fma2(hb, wb2, acc[r][2]);
                acc[r][3] = fma2(hb, wb3, acc[r][3]);
            }
        }

        // epilogue: 2 STG.128 per row
        #pragma unroll
        for (int r = 0; r < 8; r++) {
            const long row = (long)blockIdx.x * (CHUNKS * CROWS)
                           + c * CROWS + warp * 8 + r;   // row = t*B + b
            const int  t   = (int)(row >> 10);            // B = 1024
            const int  b   = (int)(row & 1023);
            float* obase = out + (((long)b * TT + t) * VV);
            const float2 f0 = unpack2(acc[r][0]);
            const float2 f1 = unpack2(acc[r][1]);
            const float2 f2 = unpack2(acc[r][2]);
            const float2 f3 = unpack2(acc[r][3]);
            ((float4*)(obase))[lane]      = make_float4(f0.x, f0.y, f1.x, f1.y);
            ((float4*)(obase))[32 + lane] = make_float4(f2.x, f2.y, f3.x, f3.y);
        }

        __syncthreads();   // all reads of buf c&1 done before it's refilled
    }
}

// ---------------------------------------------------------------------------
// kernel_launch
// inputs: 0:X int32[B,T]  1:W_xh f32[V,H]  2:W_hh f32[H,H]  3:b_h f32[H]
//         4:W_hq f32[H,V] 5:b_q f32[V]     out: f32[B,T,V]
// ---------------------------------------------------------------------------
extern "C" void kernel_launch(void* const* d_in, const int* in_sizes, int n_in,
                              void* d_out, int out_size)
{
    const int*   X   = (const int*)d_in[0];
    const float* Wxh = (const float*)d_in[1];
    const float* Whh = (const float*)d_in[2];
    const float* bh  = (const float*)d_in[3];
    const float* Whq = (const float*)d_in[4];
    const float* bq  = (const float*)d_in[5];
    float*       out = (float*)d_out;

    rnn_recurrence<<<BB / 8, 256>>>(X, Wxh, Whh, bh);
    rnn_logits<<<(TT * BB) / (CHUNKS * CROWS), 256>>>(Whq, bq, out);
}